// round 2
// baseline (speedup 1.0000x reference)
#include <cuda_runtime.h>
#include <cuda_bf16.h>
#include <cstdint>

#define NROWS 8192
#define IN_F  4096
#define OUT_F 4096
#define RANK  1024

#define BM 128
#define BN 128
#define BK 32
#define STR 40   // smem row stride (bf16 elems), padded for conflict-free frag loads

// ---------------- scratch (static device globals; no runtime allocation) ----------------
__device__ __nv_bfloat16 g_xh[(size_t)NROWS * IN_F];   // x hi part
__device__ __nv_bfloat16 g_xl[(size_t)NROWS * IN_F];   // x lo part
__device__ __nv_bfloat16 g_vh[(size_t)RANK  * IN_F];   // Vh integer weights (d - zp), exact in bf16
__device__ __nv_bfloat16 g_u [(size_t)OUT_F * RANK];   // U integer weights
__device__ __nv_bfloat16 g_hh[(size_t)NROWS * RANK];   // h_scaled hi part
__device__ __nv_bfloat16 g_hl[(size_t)NROWS * RANK];   // h_scaled lo part
__device__ float         g_cs[RANK];                   // per-rank fused scale: Vh_s * S_s * (S_d - S_zp)

// ---------------- prep kernels ----------------
__global__ void k_convert_x(const float* __restrict__ x, int n4) {
    int i = blockIdx.x * blockDim.x + threadIdx.x;
    if (i >= n4) return;
    float4 v = ((const float4*)x)[i];
    float f[4] = {v.x, v.y, v.z, v.w};
    __nv_bfloat16 h[4], l[4];
#pragma unroll
    for (int j = 0; j < 4; ++j) {
        h[j] = __float2bfloat16(f[j]);
        l[j] = __float2bfloat16(f[j] - __bfloat162float(h[j]));
    }
    ((__nv_bfloat162*)g_xh)[i*2 + 0] = __nv_bfloat162(h[0], h[1]);
    ((__nv_bfloat162*)g_xh)[i*2 + 1] = __nv_bfloat162(h[2], h[3]);
    ((__nv_bfloat162*)g_xl)[i*2 + 0] = __nv_bfloat162(l[0], l[1]);
    ((__nv_bfloat162*)g_xl)[i*2 + 1] = __nv_bfloat162(l[2], l[3]);
}

template<int W>
__global__ void k_convert_w(const int* __restrict__ src, const float* __restrict__ zp, int n) {
    int i = blockIdx.x * blockDim.x + threadIdx.x;
    if (i >= n) return;
    float z = zp[0];
    __nv_bfloat16* dst = (W == 0) ? g_vh : g_u;
    dst[i] = __float2bfloat16((float)src[i] - z);   // integer in [-128,127]: exact in bf16
}

__global__ void k_colscale(const int* __restrict__ Sd, const float* __restrict__ vhs,
                           const float* __restrict__ ss, const float* __restrict__ szp) {
    int r = blockIdx.x * blockDim.x + threadIdx.x;
    if (r < RANK)
        g_cs[r] = vhs[0] * ss[0] * ((float)Sd[r] - szp[0]);
}

// ---------------- GEMM (mma.sync bf16, hi/lo two-pass K loop) ----------------
// MODE 0: h_scaled[N,RANK] = ((xh+xl) @ Vh_int^T) * colscale  -> stored as bf16 hi/lo
// MODE 1: y[N,OUT] = ((hh+hl) @ U_int^T) * U_scale + bias     -> f32 out
template<int MODE>
__global__ void __launch_bounds__(256)
gemm_kernel(const float* __restrict__ sc, const float* __restrict__ bias, float* __restrict__ out) {
    constexpr int K  = (MODE == 0) ? IN_F : RANK;
    constexpr int NN = (MODE == 0) ? RANK : OUT_F;
    constexpr int KT = K / BK;
    constexpr int T  = 2 * KT;        // hi pass then lo pass

    const __nv_bfloat16* Ah = (MODE == 0) ? g_xh : g_hh;
    const __nv_bfloat16* Al = (MODE == 0) ? g_xl : g_hl;
    const __nv_bfloat16* Bw = (MODE == 0) ? g_vh : g_u;

    __shared__ __nv_bfloat16 sA[2][BM * STR];
    __shared__ __nv_bfloat16 sB[2][BN * STR];

    const int tid  = threadIdx.x;
    const int lane = tid & 31;
    const int warp = tid >> 5;
    const int wm   = warp & 3;        // 4 warps along M
    const int wn   = warp >> 2;       // 2 warps along N
    const int bmBase = blockIdx.x * BM;
    const int bnBase = blockIdx.y * BN;

    float acc[2][8][4];
#pragma unroll
    for (int a = 0; a < 2; ++a)
#pragma unroll
        for (int b = 0; b < 8; ++b)
#pragma unroll
            for (int c = 0; c < 4; ++c) acc[a][b][c] = 0.f;

    // gmem tile-load mapping: 512 uint4 vectors per (A|B) tile, 2 per thread
    const int v0 = tid,      ar0 = v0 >> 2, ac0 = (v0 & 3) * 8;
    const int v1 = tid + 256, ar1 = v1 >> 2, ac1 = (v1 & 3) * 8;

    uint4 ra0, ra1, rb0, rb1;

    // prefetch tile 0 (hi pass, kk = 0)
    {
        const __nv_bfloat16* A = Ah;
        ra0 = *(const uint4*)(A  + (size_t)(bmBase + ar0) * K + ac0);
        ra1 = *(const uint4*)(A  + (size_t)(bmBase + ar1) * K + ac1);
        rb0 = *(const uint4*)(Bw + (size_t)(bnBase + ar0) * K + ac0);
        rb1 = *(const uint4*)(Bw + (size_t)(bnBase + ar1) * K + ac1);
    }
    *(uint4*)&sA[0][ar0 * STR + ac0] = ra0;
    *(uint4*)&sA[0][ar1 * STR + ac1] = ra1;
    *(uint4*)&sB[0][ar0 * STR + ac0] = rb0;
    *(uint4*)&sB[0][ar1 * STR + ac1] = rb1;
    __syncthreads();

    for (int t = 0; t < T; ++t) {
        const int cur = t & 1;

        // issue next tile's global loads early (register staging)
        if (t + 1 < T) {
            const int t1 = t + 1;
            const __nv_bfloat16* A = (t1 < KT) ? Ah : Al;
            const int kk = (t1 < KT ? t1 : t1 - KT) * BK;
            ra0 = *(const uint4*)(A  + (size_t)(bmBase + ar0) * K + kk + ac0);
            ra1 = *(const uint4*)(A  + (size_t)(bmBase + ar1) * K + kk + ac1);
            rb0 = *(const uint4*)(Bw + (size_t)(bnBase + ar0) * K + kk + ac0);
            rb1 = *(const uint4*)(Bw + (size_t)(bnBase + ar1) * K + kk + ac1);
        }

        // compute on current smem tiles
        const __nv_bfloat16* pa = sA[cur];
        const __nv_bfloat16* pb = sB[cur];
#pragma unroll
        for (int ks = 0; ks < 2; ++ks) {
            uint32_t af[2][4], bfr[8][2];
            const int fr = lane >> 2;
            const int fc = ks * 16 + (lane & 3) * 2;
#pragma unroll
            for (int mt = 0; mt < 2; ++mt) {
                const int base = (wm * 32 + mt * 16 + fr) * STR + fc;
                af[mt][0] = *(const uint32_t*)&pa[base];
                af[mt][1] = *(const uint32_t*)&pa[base + 8 * STR];
                af[mt][2] = *(const uint32_t*)&pa[base + 8];
                af[mt][3] = *(const uint32_t*)&pa[base + 8 * STR + 8];
            }
#pragma unroll
            for (int nt = 0; nt < 8; ++nt) {
                const int base = (wn * 64 + nt * 8 + fr) * STR + fc;
                bfr[nt][0] = *(const uint32_t*)&pb[base];
                bfr[nt][1] = *(const uint32_t*)&pb[base + 8];
            }
#pragma unroll
            for (int mt = 0; mt < 2; ++mt)
#pragma unroll
                for (int nt = 0; nt < 8; ++nt) {
                    asm volatile(
                        "mma.sync.aligned.m16n8k16.row.col.f32.bf16.bf16.f32 "
                        "{%0,%1,%2,%3}, {%4,%5,%6,%7}, {%8,%9}, {%0,%1,%2,%3};\n"
                        : "+f"(acc[mt][nt][0]), "+f"(acc[mt][nt][1]),
                          "+f"(acc[mt][nt][2]), "+f"(acc[mt][nt][3])
                        : "r"(af[mt][0]), "r"(af[mt][1]), "r"(af[mt][2]), "r"(af[mt][3]),
                          "r"(bfr[nt][0]), "r"(bfr[nt][1]));
                }
        }

        if (t + 1 < T) {
            const int nb = (t + 1) & 1;
            *(uint4*)&sA[nb][ar0 * STR + ac0] = ra0;
            *(uint4*)&sA[nb][ar1 * STR + ac1] = ra1;
            *(uint4*)&sB[nb][ar0 * STR + ac0] = rb0;
            *(uint4*)&sB[nb][ar1 * STR + ac1] = rb1;
        }
        __syncthreads();
    }

    // ---------------- epilogue ----------------
    const int er = lane >> 2;
    const int ec = (lane & 3) * 2;
    float us = 0.f;
    if (MODE == 1) us = sc[0];

#pragma unroll
    for (int mt = 0; mt < 2; ++mt) {
#pragma unroll
        for (int nt = 0; nt < 8; ++nt) {
            const int row = bmBase + wm * 32 + mt * 16 + er;
            const int col = bnBase + wn * 64 + nt * 8 + ec;
            if (MODE == 0) {
                const float s0 = g_cs[col], s1 = g_cs[col + 1];
#pragma unroll
                for (int h = 0; h < 2; ++h) {           // row half: +0, +8
                    const int rr = row + h * 8;
                    const float h0 = acc[mt][nt][2 * h + 0] * s0;
                    const float h1 = acc[mt][nt][2 * h + 1] * s1;
                    const __nv_bfloat16 H0 = __float2bfloat16(h0);
                    const __nv_bfloat16 H1 = __float2bfloat16(h1);
                    const __nv_bfloat16 L0 = __float2bfloat16(h0 - __bfloat162float(H0));
                    const __nv_bfloat16 L1 = __float2bfloat16(h1 - __bfloat162float(H1));
                    *(__nv_bfloat162*)&g_hh[(size_t)rr * RANK + col] = __nv_bfloat162(H0, H1);
                    *(__nv_bfloat162*)&g_hl[(size_t)rr * RANK + col] = __nv_bfloat162(L0, L1);
                }
            } else {
                const float b0 = bias[col], b1 = bias[col + 1];
#pragma unroll
                for (int h = 0; h < 2; ++h) {
                    const int rr = row + h * 8;
                    float2 y;
                    y.x = acc[mt][nt][2 * h + 0] * us + b0;
                    y.y = acc[mt][nt][2 * h + 1] * us + b1;
                    *(float2*)&out[(size_t)rr * OUT_F + col] = y;
                }
            }
        }
    }
}

// ---------------- launch ----------------
extern "C" void kernel_launch(void* const* d_in, const int* in_sizes, int n_in,
                              void* d_out, int out_size) {
    const float* x    = (const float*)d_in[0];
    const int*   Ud   = (const int*)  d_in[1];
    const float* Us   = (const float*)d_in[2];
    const float* Uzp  = (const float*)d_in[3];
    const int*   Sd   = (const int*)  d_in[4];
    const float* Ss   = (const float*)d_in[5];
    const float* Szp  = (const float*)d_in[6];
    const int*   Vhd  = (const int*)  d_in[7];
    const float* Vhs  = (const float*)d_in[8];
    const float* Vhzp = (const float*)d_in[9];
    const float* bias = (const float*)d_in[10];
    float* out = (float*)d_out;

    (void)in_sizes; (void)n_in; (void)out_size; (void)Uzp;

    const int nx4 = NROWS * IN_F / 4;
    k_convert_x<<<(nx4 + 255) / 256, 256>>>(x, nx4);
    k_convert_w<0><<<(RANK * IN_F + 255) / 256, 256>>>(Vhd, Vhzp, RANK * IN_F);
    k_convert_w<1><<<(OUT_F * RANK + 255) / 256, 256>>>(Ud, Uzp, OUT_F * RANK);
    k_colscale<<<(RANK + 255) / 256, 256>>>(Sd, Vhs, Ss, Szp);

    gemm_kernel<0><<<dim3(NROWS / BM, RANK  / BN), 256>>>(nullptr, nullptr, nullptr);
    gemm_kernel<1><<<dim3(NROWS / BM, OUT_F / BN), 256>>>(Us, bias, out);
}